// round 2
// baseline (speedup 1.0000x reference)
#include <cuda_runtime.h>
#include <cuda_bf16.h>
#include <cstdint>

// Problem constants
#define B_      8
#define S_      512
#define E_      128
#define D_      512
#define VOCAB_  32000
#define LN_EPS  1e-5f

// Scratch for m[b][o][i]  (8*512*128 floats = 2MB) — static __device__ (no allocs)
__device__ float g_m[B_ * D_ * E_];

// Packed f32x2 FMA (Blackwell sm_10x): d = a*b + c on both 32-bit halves.
__device__ __forceinline__ unsigned long long ffma2(
    unsigned long long a, unsigned long long b, unsigned long long c)
{
    unsigned long long d;
    asm("fma.rn.f32x2 %0, %1, %2, %3;" : "=l"(d) : "l"(a), "l"(b), "l"(c));
    return d;
}

__device__ __forceinline__ float fold2(unsigned long long v)
{
    const float lo = __int_as_float((int)(unsigned)(v & 0xffffffffULL));
    const float hi = __int_as_float((int)(unsigned)(v >> 32));
    return lo + hi;
}

// ---------------------------------------------------------------------------
// Kernel A: m[b,o,i] = sum_j W[o,i,j] * king_emb_table[king_id[b], j]
// One block per o (512 blocks), 128 threads (4 warps). HBM-bound (33.5 MB W).
// Warp lane layout: lane = g*8 + b (g = j-quarter, b = batch). Each lane keeps
// its 32 king values in registers; per i-row: 8 coalesced float4 W loads,
// 32 FMAs, 2-shuffle reduction over g. Lanes 0..7 hold m[b][o][i].
// ---------------------------------------------------------------------------
__global__ __launch_bounds__(128, 8) void compute_m_kernel(
    const float* __restrict__ W,
    const float* __restrict__ king_tab,
    const int*   __restrict__ king_id)
{
    const int o    = blockIdx.x;
    const int t    = threadIdx.x;
    const int lane = t & 31;
    const int w    = t >> 5;     // warp 0..3
    const int g    = lane >> 3;  // j-quarter 0..3
    const int b    = lane & 7;   // batch 0..7

    __shared__ float m_s[8][132];  // padded: conflict-free column writes

    float kr[32];
    {
        const int kid = king_id[b];
        const float4* kp = (const float4*)(king_tab + (size_t)kid * E_ + g * 32);
        #pragma unroll
        for (int q = 0; q < 8; q++) {
            float4 v = kp[q];
            kr[q * 4 + 0] = v.x; kr[q * 4 + 1] = v.y;
            kr[q * 4 + 2] = v.z; kr[q * 4 + 3] = v.w;
        }
    }

    const float4* Wo = (const float4*)(W + (size_t)o * E_ * E_);

    for (int i = w; i < E_; i += 4) {
        const float4* Wrow = Wo + i * (E_ / 4);
        float acc = 0.f;
        #pragma unroll
        for (int q = 0; q < 8; q++) {
            float4 v = Wrow[g * 8 + q];      // j = g*32 + q*4 .. +3
            acc += v.x * kr[q * 4 + 0];
            acc += v.y * kr[q * 4 + 1];
            acc += v.z * kr[q * 4 + 2];
            acc += v.w * kr[q * 4 + 3];
        }
        acc += __shfl_xor_sync(0xffffffffu, acc, 8);
        acc += __shfl_xor_sync(0xffffffffu, acc, 16);
        if (lane < 8) m_s[b][i] = acc;
    }
    __syncthreads();

    #pragma unroll
    for (int bb = 0; bb < 8; bb++)
        g_m[(size_t)bb * D_ * E_ + (size_t)o * E_ + t] = m_s[bb][t];
}

// ---------------------------------------------------------------------------
// Kernel B: fused gather + GEMM + bias + LayerNorm, packed-f32x2 mainloop.
//   x[b,s,o] = sum_i emb[kid, seq[b,s], i] * m[b,o,i] + bias[o];  out = LN(x)
// Block = (b, 32-row s-tile) -> 128 blocks, 256 threads.
// Thread (sg = t>>6, og = t&63): 8s x 8o register tile, o = og + 64*oo
// (stride-64 o's -> perfectly coalesced stores). K dimension packed 2-wide:
// acc2[ss][oo] holds (even-k partial, odd-k partial); both fma.f32x2 operands
// come straight out of LDS.128 / LDG.128 halves — zero pack instructions.
// ---------------------------------------------------------------------------
#define ST_ 32

__global__ __launch_bounds__(256, 1) void gemm_ln_kernel(
    const int*   __restrict__ seq,
    const int*   __restrict__ king_id,
    const float* __restrict__ emb,
    const float* __restrict__ bias,
    const float* __restrict__ gamma,
    const float* __restrict__ beta,
    float*       __restrict__ out)
{
    const int blk = blockIdx.x;          // 0..127
    const int b   = blk >> 4;            // 16 s-tiles per batch
    const int s0  = (blk & 15) * ST_;
    const int t   = threadIdx.x;
    const int og  = t & 63;
    const int sg  = t >> 6;

    __shared__ float A_s[ST_][E_];        // 16 KB, 16B-aligned rows
    __shared__ float red[2][ST_][66];     // padded for conflict-free phase-2 reads
    __shared__ float mu_s[ST_], rs_s[ST_];

    // --- Gather embedding rows for this s-tile into smem (coalesced per row)
    {
        const int kid = king_id[b];
        const float* etab = emb + (size_t)kid * VOCAB_ * E_;
        for (int r = t; r < ST_ * (E_ / 4); r += 256) {
            const int s  = r >> 5;        // E_/4 = 32 float4 per row
            const int i4 = r & 31;
            const int tok = seq[b * S_ + s0 + s];
            ((float4*)A_s[s])[i4] = ((const float4*)(etab + (size_t)tok * E_))[i4];
        }
    }
    __syncthreads();

    const float* Mb = g_m + (size_t)b * D_ * E_;

    unsigned long long acc2[8][8];
    #pragma unroll
    for (int ss = 0; ss < 8; ss++)
        #pragma unroll
        for (int oo = 0; oo < 8; oo++)
            acc2[ss][oo] = 0ULL;

    const ulonglong2* Mp[8];
    #pragma unroll
    for (int oo = 0; oo < 8; oo++)
        Mp[oo] = (const ulonglong2*)(Mb + (size_t)(og + 64 * oo) * E_);

    // --- K loop: 32 steps of 4 k-elements (= 2 packed k-pairs) each
    #pragma unroll 4
    for (int i4 = 0; i4 < E_ / 4; i4++) {
        ulonglong2 mv[8];
        #pragma unroll
        for (int oo = 0; oo < 8; oo++) mv[oo] = Mp[oo][i4];
        #pragma unroll
        for (int ss = 0; ss < 8; ss++) {
            const ulonglong2 a2 = ((const ulonglong2*)A_s[sg * 8 + ss])[i4];
            #pragma unroll
            for (int oo = 0; oo < 8; oo++) {
                acc2[ss][oo] = ffma2(a2.x, mv[oo].x, acc2[ss][oo]);
                acc2[ss][oo] = ffma2(a2.y, mv[oo].y, acc2[ss][oo]);
            }
        }
    }

    // --- fold packed halves + bias
    float accf[8][8];
    float bo[8];
    #pragma unroll
    for (int oo = 0; oo < 8; oo++) bo[oo] = bias[og + 64 * oo];
    #pragma unroll
    for (int ss = 0; ss < 8; ss++)
        #pragma unroll
        for (int oo = 0; oo < 8; oo++)
            accf[ss][oo] = fold2(acc2[ss][oo]) + bo[oo];

    // --- LN reduction phase 1: per-thread partials over its 8 o's
    #pragma unroll
    for (int ss = 0; ss < 8; ss++) {
        float ls = 0.f, lq = 0.f;
        #pragma unroll
        for (int oo = 0; oo < 8; oo++) {
            const float v = accf[ss][oo];
            ls += v;
            lq += v * v;
        }
        red[0][sg * 8 + ss][og] = ls;
        red[1][sg * 8 + ss][og] = lq;
    }
    __syncthreads();

    // --- LN reduction phase 2: 8 threads per s reduce 64 partials
    {
        const int s = t >> 3;     // 0..31
        const int k = t & 7;
        float ps = 0.f, pq = 0.f;
        #pragma unroll
        for (int j = 0; j < 8; j++) {
            ps += red[0][s][k + 8 * j];
            pq += red[1][s][k + 8 * j];
        }
        #pragma unroll
        for (int d = 1; d < 8; d <<= 1) {
            ps += __shfl_xor_sync(0xffffffffu, ps, d);
            pq += __shfl_xor_sync(0xffffffffu, pq, d);
        }
        if (k == 0) {
            const float mean = ps * (1.f / (float)D_);
            const float var  = pq * (1.f / (float)D_) - mean * mean;
            mu_s[s] = mean;
            rs_s[s] = rsqrtf(var + LN_EPS);
        }
    }
    __syncthreads();

    // --- normalize + affine + coalesced store (lane-adjacent o's)
    float go[8], be[8];
    #pragma unroll
    for (int oo = 0; oo < 8; oo++) {
        go[oo] = gamma[og + 64 * oo];
        be[oo] = beta[og + 64 * oo];
    }
    #pragma unroll
    for (int ss = 0; ss < 8; ss++) {
        const int s = sg * 8 + ss;
        const float mu = mu_s[s];
        const float rs = rs_s[s];
        float* orow = out + ((size_t)(b * S_ + s0 + s)) * D_;
        #pragma unroll
        for (int oo = 0; oo < 8; oo++) {
            orow[og + 64 * oo] = (accf[ss][oo] - mu) * rs * go[oo] + be[oo];
        }
    }
}

// ---------------------------------------------------------------------------
extern "C" void kernel_launch(void* const* d_in, const int* in_sizes, int n_in,
                              void* d_out, int out_size)
{
    const int*   seq      = (const int*)  d_in[0];  // (8, 512) int32
    const int*   king_id  = (const int*)  d_in[1];  // (8,) int32
    const float* emb      = (const float*)d_in[2];  // (27, 32000, 128)
    const float* king_tab = (const float*)d_in[3];  // (27, 128)
    const float* W        = (const float*)d_in[4];  // (512, 128, 128)
    const float* bias     = (const float*)d_in[5];  // (512,)
    const float* gamma    = (const float*)d_in[6];  // (512,)
    const float* beta     = (const float*)d_in[7];  // (512,)
    float*       out      = (float*)d_out;          // (8, 512, 512)

    compute_m_kernel<<<D_, 128>>>(W, king_tab, king_id);
    gemm_ln_kernel<<<B_ * (S_ / ST_), 256>>>(seq, king_id, emb, bias, gamma, beta, out);
}